// round 14
// baseline (speedup 1.0000x reference)
#include <cuda_runtime.h>
#include <cuda_fp16.h>
#include <math.h>
#include <stdint.h>

#define T_     8
#define NTOK_  32768
#define D_     128
#define L_     8
#define CD_    64
#define STRB   272          /* fp16 tile row stride in bytes (136 elems) */

// ---------------- device scratch (zero-initialized at module load) ----------------
__device__ __align__(16) float g_hsum[T_ * L_ * D_];
__device__ __align__(16) float g_comp[T_ * L_ * CD_];
__device__ int   g_cnt [T_ * L_];
__device__ int   g_bar;
__device__ float g_c1  [D_];            // sum_k lnw_k * w1[k,e]
__device__ float g_c2b [D_];            // sum_k lnb_k * w1[k,e] + b1[e]
__device__ __align__(16) __half g_w1img[D_ * 136];  // (lnw .* W1)^T padded [e][k]

// ---------------- helpers ----------------
__device__ __forceinline__ uint32_t smem_u32(const void* p) {
    uint32_t a;
    asm("{ .reg .u64 t; cvta.to.shared.u64 t, %1; cvt.u32.u64 %0, t; }" : "=r"(a) : "l"(p));
    return a;
}
#define LDSM4(f, a) asm volatile( \
    "ldmatrix.sync.aligned.m8n8.x4.shared.b16 {%0,%1,%2,%3}, [%4];" \
    : "=r"((f)[0]), "=r"((f)[1]), "=r"((f)[2]), "=r"((f)[3]) : "r"(a))
#define LDSM2T(f, a) asm volatile( \
    "ldmatrix.sync.aligned.m8n8.x2.trans.shared.b16 {%0,%1}, [%2];" \
    : "=r"((f)[0]), "=r"((f)[1]) : "r"(a))
// fp32-accumulate (MMA2 bucket sums)
__device__ __forceinline__ void mma16816(float* c, const uint32_t* a, const uint32_t* b) {
    asm volatile(
        "mma.sync.aligned.m16n8k16.row.col.f32.f16.f16.f32 "
        "{%0,%1,%2,%3}, {%4,%5,%6,%7}, {%8,%9}, {%0,%1,%2,%3};"
        : "+f"(c[0]), "+f"(c[1]), "+f"(c[2]), "+f"(c[3])
        : "r"(a[0]), "r"(a[1]), "r"(a[2]), "r"(a[3]), "r"(b[0]), "r"(b[1]));
}
// fp16-accumulate (MMA1 main GEMM)
__device__ __forceinline__ void mma16816h(uint32_t* c, const uint32_t* a, const uint32_t* b) {
    asm volatile(
        "mma.sync.aligned.m16n8k16.row.col.f16.f16.f16.f16 "
        "{%0,%1}, {%2,%3,%4,%5}, {%6,%7}, {%0,%1};"
        : "+r"(c[0]), "+r"(c[1])
        : "r"(a[0]), "r"(a[1]), "r"(a[2]), "r"(a[3]), "r"(b[0]), "r"(b[1]));
}
__device__ __forceinline__ uint32_t packhf2(float lo, float hi) {
    uint32_t r;
    asm("cvt.rn.f16x2.f32 %0, %1, %2;" : "=r"(r) : "f"(hi), "f"(lo));
    return r;
}
__device__ __forceinline__ float gelu_exact(float z) {
    return 0.5f * z * (1.0f + erff(z * 0.70710678118654752440f));
}
// fast exact-form gelu: z*(0.5 + z*q(z^2)), q = Taylor of 0.5*erf(z/sqrt2)/z.
__device__ __forceinline__ float gelu_fast(float z) {
    float zc = fminf(fmaxf(z, -2.5f), 2.5f);
    float t  = zc * zc;
    float q  =              -4.1226618343100706e-8f;
    q = fmaf(q, t,           6.6596941016452680e-7f);
    q = fmaf(q, t,          -9.4444668655640310e-6f);
    q = fmaf(q, t,           1.1543700706522937e-4f);
    q = fmaf(q, t,          -1.1873282154804544e-3f);
    q = fmaf(q, t,           9.9735570100358180e-3f);
    q = fmaf(q, t,          -6.6490380066905450e-2f);
    q = fmaf(q, t,           3.9894228040143270e-1f);
    return z * fmaf(zc, q, 0.5f);
}
__device__ __forceinline__ float wred(float v) {
    #pragma unroll
    for (int o = 16; o; o >>= 1) v += __shfl_down_sync(0xffffffffu, v, o);
    return v;
}

// SMEM layout (bytes)
#define OFF_STAT 64          /* 128 x float2 (m, rstd)          */
#define OFF_C1   1088        /* 512B                            */
#define OFF_C2B  1600        /* 512B                            */
#define OFF_MASK 2112        /* 16 x 272 = 4352B                */
#define OFF_XN   6528        /* 128 x 272 (X fp16, later P)     */
#define OFF_W    41344       /* 128 x 272 (W1' ^T fp16)         */
#define SMEM_SZ  76160

// -------- kernel 0: W1' image + c1/c2b vectors --------
__global__ void k_prep(const float* __restrict__ w1, const float* __restrict__ lnw,
                       const float* __restrict__ lnb, const float* __restrict__ b1) {
    __shared__ float pa[512], pb[512];
    const int b = blockIdx.x, tid = threadIdx.x;
    if (b < 32) {
        int i = b * 512 + tid;
        int e = i & 127, k = i >> 7;
        g_w1img[e * 136 + k] = __float2half(lnw[k] * w1[k * 128 + e]);
    } else {
        const int e = tid & 127, j = tid >> 7;
        float a = 0.f, c = 0.f;
        #pragma unroll
        for (int kk = 0; kk < 32; ++kk) {
            int k = j * 32 + kk;
            float wv = w1[k * 128 + e];
            a = fmaf(lnw[k], wv, a);
            c = fmaf(lnb[k], wv, c);
        }
        pa[tid] = a; pb[tid] = c;
        __syncthreads();
        if (tid < 128) {
            g_c1[tid]  = pa[tid] + pa[tid + 128] + pa[tid + 256] + pa[tid + 384];
            g_c2b[tid] = pb[tid] + pb[tid + 128] + pb[tid + 256] + pb[tid + 384] + b1[tid];
        }
    }
}

// -------- kernel 1: x -> HMMA (32x32 tiles) -> LN-affine+gelu -> mask-HMMA sums --------
__global__ __launch_bounds__(512, 3) void k_main(
    const float* __restrict__ x, const int* __restrict__ node_idx,
    const int* __restrict__ ne_p)
{
    extern __shared__ char sm[];
    const uint32_t smb = smem_u32(sm);
    const int tid  = threadIdx.x;
    const int w    = tid >> 5, lane = tid & 31;
    const int t    = blockIdx.y;
    const int base = blockIdx.x * 128;

    float2* stat = (float2*)(sm + OFF_STAT);
    float*  c1s  = (float*)(sm + OFF_C1);
    float*  c2bs = (float*)(sm + OFF_C2B);

    // ---- phase A (single barrier at the end) ----
    if (tid < 128)      c1s[tid] = g_c1[tid];
    else if (tid < 256) c2bs[tid - 128] = g_c2b[tid - 128];
    {
        const int4* src = (const int4*)g_w1img;
        int4* dst = (int4*)(sm + OFF_W);
        #pragma unroll
        for (int i = tid; i < 2176; i += 512) dst[i] = src[i];
    }
    // mask column-owned by thread tid (<128): zero 16 rows then set own 1.
    // hist via warp ballots straight to global (no smem, no ordering hazard).
    if (tid < 128) {
        int gsz = ne_p[0] >> 3;
        int gid = node_idx[t * NTOK_ + base + tid] / gsz;
        #pragma unroll
        for (int l = 0; l < 16; ++l)
            *(__half*)(sm + OFF_MASK + l * STRB + tid * 2) = __ushort_as_half((unsigned short)0);
        *(__half*)(sm + OFF_MASK + gid * STRB + tid * 2) = __float2half(1.0f);
        #pragma unroll
        for (int l = 0; l < 8; ++l) {
            unsigned bm = __ballot_sync(0xffffffffu, gid == l);
            if (lane == l) atomicAdd(&g_cnt[t * L_ + l], __popc(bm));
        }
    }
    // coalesced streaming x load, 2 chunks of 4 rows (reg diet for occ-3)
    #pragma unroll
    for (int half = 0; half < 2; ++half) {
        float4 xv[4];
        const float4* xp = (const float4*)(x + ((size_t)t * NTOK_ + base + w * 8 + half * 4) * D_) + lane;
        #pragma unroll
        for (int i = 0; i < 4; ++i) xv[i] = __ldcs(xp + i * 32);
        char* rowp = sm + OFF_XN + (w * 8 + half * 4) * STRB + lane * 8;
        #pragma unroll
        for (int i = 0; i < 4; ++i)
            *(uint2*)(rowp + i * STRB) =
                make_uint2(packhf2(xv[i].x, xv[i].y), packhf2(xv[i].z, xv[i].w));
        #pragma unroll
        for (int i = 0; i < 4; ++i) {
            float s  = xv[i].x + xv[i].y + xv[i].z + xv[i].w;
            float s2 = xv[i].x * xv[i].x + xv[i].y * xv[i].y
                     + xv[i].z * xv[i].z + xv[i].w * xv[i].w;
            #pragma unroll
            for (int o = 16; o; o >>= 1) {
                s  += __shfl_down_sync(0xffffffffu, s,  o);
                s2 += __shfl_down_sync(0xffffffffu, s2, o);
            }
            if (lane == 0) {
                float m    = s * (1.0f / 128.0f);
                float rstd = rsqrtf(s2 * (1.0f / 128.0f) - m * m + 1e-5f);
                stat[w * 8 + half * 4 + i] = make_float2(m, rstd);
            }
        }
    }
    __syncthreads();   // X, W, mask, stats, consts all ready

    // ---- MMA1: G[128 tok][128 hid] = X @ W1' (fp16 acc), 32x32 warp tiles ----
    const int mrow = (w & 3) * 32;
    const int ncol = (w >> 2) * 32;
    const int lr = lane & 7, lg = lane >> 3;

    uint32_t acc[8][2];
    #pragma unroll
    for (int j = 0; j < 8; ++j) { acc[j][0] = 0u; acc[j][1] = 0u; }

    uint32_t aA0 = smb + OFF_XN + (mrow + lr + (lg & 1) * 8) * STRB + (lg >> 1) * 16;
    uint32_t aA1 = aA0 + 16 * STRB;
    uint32_t aB0 = smb + OFF_W + (ncol + lr + (lane >> 4) * 8) * STRB + ((lane >> 3) & 1) * 16;
    uint32_t aB1 = aB0 + 16 * STRB;

    #pragma unroll
    for (int ks = 0; ks < 8; ++ks) {
        uint32_t af0[4], af1[4], bf0[4], bf1[4];
        LDSM4(af0, aA0); aA0 += 32;
        LDSM4(af1, aA1); aA1 += 32;
        LDSM4(bf0, aB0); aB0 += 32;
        LDSM4(bf1, aB1); aB1 += 32;
        mma16816h(acc[0], af0, bf0);
        mma16816h(acc[1], af0, bf0 + 2);
        mma16816h(acc[2], af0, bf1);
        mma16816h(acc[3], af0, bf1 + 2);
        mma16816h(acc[4], af1, bf0);
        mma16816h(acc[5], af1, bf0 + 2);
        mma16816h(acc[6], af1, bf1);
        mma16816h(acc[7], af1, bf1 + 2);
    }
    __syncthreads();   // all warps done reading X tile before overwrite with P

    // ---- epilogue: h = r*g - (r*m)*c1 + c2b ; P = gelu_fast(h) fp16 ----
    #pragma unroll
    for (int ti = 0; ti < 2; ++ti) {
        const int row0 = mrow + 16 * ti + (lane >> 2);
        float2 st0 = stat[row0], st1 = stat[row0 + 8];
        float r0f = st0.y, rm0 = st0.y * st0.x;
        float r1f = st1.y, rm1 = st1.y * st1.x;
        char* prow0 = sm + OFF_XN + row0 * STRB;
        char* prow1 = prow0 + 8 * STRB;
        #pragma unroll
        for (int np = 0; np < 4; ++np) {
            int col = ncol + np * 8 + 2 * (lane & 3);
            float2 c1p = *(float2*)(c1s + col);
            float2 c2p = *(float2*)(c2bs + col);
            float2 q0 = __half22float2(*(__half2*)&acc[ti * 4 + np][0]);
            float2 q1 = __half22float2(*(__half2*)&acc[ti * 4 + np][1]);
            float h0 = fmaf(r0f, q0.x, fmaf(-rm0, c1p.x, c2p.x));
            float h1 = fmaf(r0f, q0.y, fmaf(-rm0, c1p.y, c2p.y));
            float h2 = fmaf(r1f, q1.x, fmaf(-rm1, c1p.x, c2p.x));
            float h3 = fmaf(r1f, q1.y, fmaf(-rm1, c1p.y, c2p.y));
            *(uint32_t*)(prow0 + col * 2) = packhf2(gelu_fast(h0), gelu_fast(h1));
            *(uint32_t*)(prow1 + col * 2) = packhf2(gelu_fast(h2), gelu_fast(h3));
        }
    }
    __syncthreads();

    // ---- MMA2: S[16 grp][128 hid] = mask @ P ; warp w owns 8 hidden cols ----
    {
        float a2[4] = {0.f, 0.f, 0.f, 0.f};
        uint32_t aM = smb + OFF_MASK + (lr + (lg & 1) * 8) * STRB + (lg >> 1) * 16;
        uint32_t aP = smb + OFF_XN + ((lane & 7) + ((lane >> 3) & 1) * 8) * STRB + w * 16;
        #pragma unroll
        for (int ks = 0; ks < 8; ++ks) {
            uint32_t mf[4], pf[2];
            LDSM4(mf, aM); aM += 32;
            LDSM2T(pf, aP); aP += 16 * STRB;
            mma16816(a2, mf, pf);
        }
        int grp = lane >> 2;
        int col = w * 8 + 2 * (lane & 3);
        float* dst = &g_hsum[(t * L_ + grp) * D_ + col];
        atomicAdd(dst,     a2[0]);
        atomicAdd(dst + 1, a2[1]);
    }
}

// -------- kernel 2 (merged tail): comp per block, last block does LN + ortho --------
__global__ __launch_bounds__(512) void k_tail(
    const float* __restrict__ w2,   const float* __restrict__ b1,
    const float* __restrict__ b2,   const int*   __restrict__ ne_p,
    const float* __restrict__ lnfw, const float* __restrict__ lnfb,
    float* __restrict__ out, int out_size)
{
    __shared__ __align__(16) float cs[T_ * L_ * CD_];   // 16KB, t-major
    __shared__ __align__(16) float mh[D_];
    __shared__ __align__(16) float part[8][CD_];
    __shared__ float Gm[64];
    __shared__ float Rs[L_], inv[L_];
    __shared__ float dots[49];
    __shared__ int   last;

    const int p   = blockIdx.x;           // t*8 + l
    const int tid = threadIdx.x;
    const int g   = ne_p[0] >> 3;
    if (tid < D_) {
        float h0 = gelu_exact(b1[tid]);
        mh[tid] = (g_hsum[p * D_ + tid] + (float)(g - g_cnt[p]) * h0) / (float)g;
    }
    __syncthreads();
    // zero-restore accumulators for next graph replay (consumed above)
    if (tid < D_) g_hsum[p * D_ + tid] = 0.f;
    if (tid == 0) g_cnt[p] = 0;

    {
        const int c = tid & 63, sl = tid >> 6;   // 8 e-slices of 16
        float a = 0.f;
        #pragma unroll
        for (int i = 0; i < 16; ++i) {
            int e = sl * 16 + i;
            a = fmaf(mh[e], w2[e * CD_ + c], a);
        }
        part[sl][c] = a;
    }
    __syncthreads();
    if (tid < CD_) {
        float s = b2[tid];
        #pragma unroll
        for (int k = 0; k < 8; ++k) s += part[k][tid];
        g_comp[p * CD_ + tid] = s;
    }

    // ---- last-block election ----
    __threadfence();
    if (tid == 0) last = (atomicAdd(&g_bar, 1) == T_ * L_ - 1);
    __syncthreads();
    if (!last) return;
    if (tid == 0) g_bar = 0;            // reset for next replay
    __threadfence();

    // ---- final LN + Gram ortho (single surviving block) ----
    {
        const float4* src = (const float4*)g_comp;
        float4* dst = (float4*)cs;
        dst[tid] = src[tid];
        dst[tid + 512] = src[tid + 512];
    }
    __syncthreads();

    const int w = tid >> 5, lane = tid & 31;
    if (w < 8) {
        const int t = w;
        const float* row = cs + t * 512;
        float s = 0.f;
        for (int i = lane; i < 512; i += 32) s += row[i];
        s = wred(s);
        float m = __shfl_sync(0xffffffffu, s, 0) * (1.0f / 512.0f);
        float v = 0.f;
        for (int i = lane; i < 512; i += 32) { float c0 = row[i] - m; v += c0 * c0; }
        v = wred(v);
        float rstd = rsqrtf(__shfl_sync(0xffffffffu, v, 0) * (1.0f / 512.0f) + 1e-5f);
        for (int i = lane; i < 512; i += 32)
            out[t * 512 + i] = (row[i] - m) * rstd * lnfw[i] + lnfb[i];
    } else {
        const int l = w - 8;
        float r = 0.f, gg = 0.f;
        for (int k = lane; k < 512; k += 32) {
            float v = cs[(k >> 6) * 512 + l * 64 + (k & 63)];
            r += v; gg += v * v;
        }
        r = wred(r); gg = wred(gg);
        if (lane == 0) { Rs[l] = r; Gm[l * 8 + l] = gg; inv[l] = rsqrtf(gg); }
    }
    __syncthreads();

    for (int pp = w; pp < 28; pp += 16) {
        int i = 0, r = pp;
        while (r >= 7 - i) { r -= 7 - i; ++i; }
        int j = i + 1 + r;
        float d = 0.f;
        for (int k = lane; k < 512; k += 32) {
            int off = (k >> 6) * 512 + (k & 63);
            d += cs[off + i * 64] * cs[off + j * 64];
        }
        d = wred(d);
        if (lane == 0) Gm[i * 8 + j] = d;
    }
    __syncthreads();

    if (tid < 49) {
        int i = tid / 7, j = tid % 7 + 1;
        int a = i < j ? i : j, b = i < j ? j : i;
        float gij = Gm[a * 8 + b];
        float num = gij * inv[i] * inv[j];
        float den = Rs[i] * inv[i] + Rs[j] * inv[j];
        float d = num / den;
        dots[tid] = d * d;
    }
    __syncthreads();
    if (tid == 0 && out_size > T_ * L_ * CD_) {
        float s = 0.f;
        #pragma unroll
        for (int pq = 0; pq < 49; ++pq) s += dots[pq];
        out[T_ * L_ * CD_] = s * (1.0f / 49.0f);
    }
}

// -------- launch --------
extern "C" void kernel_launch(void* const* d_in, const int* in_sizes, int n_in,
                              void* d_out, int out_size)
{
    const float* x    = (const float*)d_in[0];
    const float* lnw  = (const float*)d_in[1];
    const float* lnb  = (const float*)d_in[2];
    const float* w1   = (const float*)d_in[3];
    const float* b1   = (const float*)d_in[4];
    const float* w2   = (const float*)d_in[5];
    const float* b2   = (const float*)d_in[6];
    const float* lnfw = (const float*)d_in[7];
    const float* lnfb = (const float*)d_in[8];
    // d_in[9] = padded_node_mask (all-true)
    const int* node_idx = (const int*)d_in[10];
    const int* ne       = (const int*)d_in[11];
    float* out = (float*)d_out;

    cudaFuncSetAttribute(k_main, cudaFuncAttributeMaxDynamicSharedMemorySize, SMEM_SZ);

    k_prep<<<33, 512>>>(w1, lnw, lnb, b1);
    dim3 grid(NTOK_ / 128, T_);
    k_main<<<grid, 512, SMEM_SZ>>>(x, node_idx, ne);
    k_tail<<<T_ * L_, 512>>>(w2, b1, b2, ne, lnfw, lnfb, out, out_size);
}

// round 15
// speedup vs baseline: 1.0183x; 1.0183x over previous
#include <cuda_runtime.h>
#include <cuda_fp16.h>
#include <math.h>
#include <stdint.h>

#define T_     8
#define NTOK_  32768
#define D_     128
#define L_     8
#define CD_    64
#define STRB   272          /* fp16 tile row stride in bytes (136 elems) */

// ---------------- device scratch (zero-initialized at module load) ----------------
__device__ __align__(16) float g_hsum[T_ * L_ * D_];
__device__ __align__(16) float g_comp[T_ * L_ * CD_];
__device__ int   g_cnt [T_ * L_];
__device__ int   g_bar;
__device__ float g_c1  [D_];            // sum_k lnw_k * w1[k,e]
__device__ float g_c2b [D_];            // sum_k lnb_k * w1[k,e] + b1[e]
__device__ __align__(16) __half g_w1img[D_ * 136];  // (lnw .* W1)^T padded [e][k]

// ---------------- helpers ----------------
__device__ __forceinline__ uint32_t smem_u32(const void* p) {
    uint32_t a;
    asm("{ .reg .u64 t; cvta.to.shared.u64 t, %1; cvt.u32.u64 %0, t; }" : "=r"(a) : "l"(p));
    return a;
}
#define LDSM4(f, a) asm volatile( \
    "ldmatrix.sync.aligned.m8n8.x4.shared.b16 {%0,%1,%2,%3}, [%4];" \
    : "=r"((f)[0]), "=r"((f)[1]), "=r"((f)[2]), "=r"((f)[3]) : "r"(a))
#define LDSM2T(f, a) asm volatile( \
    "ldmatrix.sync.aligned.m8n8.x2.trans.shared.b16 {%0,%1}, [%2];" \
    : "=r"((f)[0]), "=r"((f)[1]) : "r"(a))
// fp32-accumulate (MMA2 bucket sums)
__device__ __forceinline__ void mma16816(float* c, const uint32_t* a, const uint32_t* b) {
    asm volatile(
        "mma.sync.aligned.m16n8k16.row.col.f32.f16.f16.f32 "
        "{%0,%1,%2,%3}, {%4,%5,%6,%7}, {%8,%9}, {%0,%1,%2,%3};"
        : "+f"(c[0]), "+f"(c[1]), "+f"(c[2]), "+f"(c[3])
        : "r"(a[0]), "r"(a[1]), "r"(a[2]), "r"(a[3]), "r"(b[0]), "r"(b[1]));
}
// fp16-accumulate (MMA1 main GEMM)
__device__ __forceinline__ void mma16816h(uint32_t* c, const uint32_t* a, const uint32_t* b) {
    asm volatile(
        "mma.sync.aligned.m16n8k16.row.col.f16.f16.f16.f16 "
        "{%0,%1}, {%2,%3,%4,%5}, {%6,%7}, {%0,%1};"
        : "+r"(c[0]), "+r"(c[1])
        : "r"(a[0]), "r"(a[1]), "r"(a[2]), "r"(a[3]), "r"(b[0]), "r"(b[1]));
}
__device__ __forceinline__ uint32_t packhf2(float lo, float hi) {
    uint32_t r;
    asm("cvt.rn.f16x2.f32 %0, %1, %2;" : "=r"(r) : "f"(hi), "f"(lo));
    return r;
}
__device__ __forceinline__ float gelu_exact(float z) {
    return 0.5f * z * (1.0f + erff(z * 0.70710678118654752440f));
}
// fast exact-form gelu: z*(0.5 + z*q(z^2)), q = Taylor of 0.5*erf(z/sqrt2)/z.
__device__ __forceinline__ float gelu_fast(float z) {
    float zc = fminf(fmaxf(z, -2.5f), 2.5f);
    float t  = zc * zc;
    float q  =              -4.1226618343100706e-8f;
    q = fmaf(q, t,           6.6596941016452680e-7f);
    q = fmaf(q, t,          -9.4444668655640310e-6f);
    q = fmaf(q, t,           1.1543700706522937e-4f);
    q = fmaf(q, t,          -1.1873282154804544e-3f);
    q = fmaf(q, t,           9.9735570100358180e-3f);
    q = fmaf(q, t,          -6.6490380066905450e-2f);
    q = fmaf(q, t,           3.9894228040143270e-1f);
    return z * fmaf(zc, q, 0.5f);
}
__device__ __forceinline__ float wred(float v) {
    #pragma unroll
    for (int o = 16; o; o >>= 1) v += __shfl_down_sync(0xffffffffu, v, o);
    return v;
}

// SMEM layout (bytes)
#define OFF_STAT 64          /* 128 x float2 (m, rstd)          */
#define OFF_C1   1088        /* 512B                            */
#define OFF_C2B  1600        /* 512B                            */
#define OFF_MASK 2112        /* 16 x 272 = 4352B                */
#define OFF_XN   6528        /* 128 x 272 (X fp16, later P)     */
#define OFF_W    41344       /* 128 x 272 (W1' ^T fp16)         */
#define SMEM_SZ  76160

// -------- kernel 0: W1' image + c1/c2b vectors --------
__global__ void k_prep(const float* __restrict__ w1, const float* __restrict__ lnw,
                       const float* __restrict__ lnb, const float* __restrict__ b1) {
    __shared__ float pa[512], pb[512];
    const int b = blockIdx.x, tid = threadIdx.x;
    if (b < 32) {
        int i = b * 512 + tid;
        int e = i & 127, k = i >> 7;
        g_w1img[e * 136 + k] = __float2half(lnw[k] * w1[k * 128 + e]);
    } else {
        const int e = tid & 127, j = tid >> 7;
        float a = 0.f, c = 0.f;
        #pragma unroll
        for (int kk = 0; kk < 32; ++kk) {
            int k = j * 32 + kk;
            float wv = w1[k * 128 + e];
            a = fmaf(lnw[k], wv, a);
            c = fmaf(lnb[k], wv, c);
        }
        pa[tid] = a; pb[tid] = c;
        __syncthreads();
        if (tid < 128) {
            g_c1[tid]  = pa[tid] + pa[tid + 128] + pa[tid + 256] + pa[tid + 384];
            g_c2b[tid] = pb[tid] + pb[tid + 128] + pb[tid + 256] + pb[tid + 384] + b1[tid];
        }
    }
}

// -------- kernel 1: x -> HMMA (32x32 tiles) -> LN-affine+gelu -> mask-HMMA sums --------
__global__ __launch_bounds__(512, 2) void k_main(
    const float* __restrict__ x, const int* __restrict__ node_idx,
    const int* __restrict__ ne_p)
{
    extern __shared__ char sm[];
    const uint32_t smb = smem_u32(sm);
    const int tid  = threadIdx.x;
    const int w    = tid >> 5, lane = tid & 31;
    const int t    = blockIdx.y;
    const int base = blockIdx.x * 128;

    float2* stat = (float2*)(sm + OFF_STAT);
    float*  c1s  = (float*)(sm + OFF_C1);
    float*  c2bs = (float*)(sm + OFF_C2B);

    // ---- phase A (single barrier at the end) ----
    if (tid < 128)      c1s[tid] = g_c1[tid];
    else if (tid < 256) c2bs[tid - 128] = g_c2b[tid - 128];
    {
        const int4* src = (const int4*)g_w1img;
        int4* dst = (int4*)(sm + OFF_W);
        #pragma unroll
        for (int i = tid; i < 2176; i += 512) dst[i] = src[i];
    }
    // mask column-owned by thread tid (<128): zero own 16-row column, set own 1.
    // hist via warp ballots straight to global (no smem hist, no extra barrier).
    if (tid < 128) {
        int gsz = ne_p[0] >> 3;
        int gid = node_idx[t * NTOK_ + base + tid] / gsz;
        #pragma unroll
        for (int l = 0; l < 16; ++l)
            *(__half*)(sm + OFF_MASK + l * STRB + tid * 2) = __ushort_as_half((unsigned short)0);
        *(__half*)(sm + OFF_MASK + gid * STRB + tid * 2) = __float2half(1.0f);
        #pragma unroll
        for (int l = 0; l < 8; ++l) {
            unsigned bm = __ballot_sync(0xffffffffu, gid == l);
            if (lane == l) atomicAdd(&g_cnt[t * L_ + l], __popc(bm));
        }
    }
    // coalesced streaming x load: warp w owns rows [8w, 8w+8)  (full MLP=8)
    float4 xv[8];
    {
        const float4* xp = (const float4*)(x + ((size_t)t * NTOK_ + base + w * 8) * D_) + lane;
        #pragma unroll
        for (int i = 0; i < 8; ++i) xv[i] = __ldcs(xp + i * 32);
    }
    {
        char* rowp = sm + OFF_XN + (w * 8) * STRB + lane * 8;
        #pragma unroll
        for (int i = 0; i < 8; ++i)
            *(uint2*)(rowp + i * STRB) =
                make_uint2(packhf2(xv[i].x, xv[i].y), packhf2(xv[i].z, xv[i].w));
    }
    #pragma unroll
    for (int i = 0; i < 8; ++i) {
        float s  = xv[i].x + xv[i].y + xv[i].z + xv[i].w;
        float s2 = xv[i].x * xv[i].x + xv[i].y * xv[i].y
                 + xv[i].z * xv[i].z + xv[i].w * xv[i].w;
        #pragma unroll
        for (int o = 16; o; o >>= 1) {
            s  += __shfl_down_sync(0xffffffffu, s,  o);
            s2 += __shfl_down_sync(0xffffffffu, s2, o);
        }
        if (lane == 0) {
            float m    = s * (1.0f / 128.0f);
            float rstd = rsqrtf(s2 * (1.0f / 128.0f) - m * m + 1e-5f);
            stat[w * 8 + i] = make_float2(m, rstd);
        }
    }
    __syncthreads();   // X, W, mask, stats, consts all ready

    // ---- MMA1: G[128 tok][128 hid] = X @ W1' (fp16 acc), 32x32 warp tiles ----
    const int mrow = (w & 3) * 32;
    const int ncol = (w >> 2) * 32;
    const int lr = lane & 7, lg = lane >> 3;

    uint32_t acc[8][2];
    #pragma unroll
    for (int j = 0; j < 8; ++j) { acc[j][0] = 0u; acc[j][1] = 0u; }

    uint32_t aA0 = smb + OFF_XN + (mrow + lr + (lg & 1) * 8) * STRB + (lg >> 1) * 16;
    uint32_t aA1 = aA0 + 16 * STRB;
    uint32_t aB0 = smb + OFF_W + (ncol + lr + (lane >> 4) * 8) * STRB + ((lane >> 3) & 1) * 16;
    uint32_t aB1 = aB0 + 16 * STRB;

    #pragma unroll
    for (int ks = 0; ks < 8; ++ks) {
        uint32_t af0[4], af1[4], bf0[4], bf1[4];
        LDSM4(af0, aA0); aA0 += 32;
        LDSM4(af1, aA1); aA1 += 32;
        LDSM4(bf0, aB0); aB0 += 32;
        LDSM4(bf1, aB1); aB1 += 32;
        mma16816h(acc[0], af0, bf0);
        mma16816h(acc[1], af0, bf0 + 2);
        mma16816h(acc[2], af0, bf1);
        mma16816h(acc[3], af0, bf1 + 2);
        mma16816h(acc[4], af1, bf0);
        mma16816h(acc[5], af1, bf0 + 2);
        mma16816h(acc[6], af1, bf1);
        mma16816h(acc[7], af1, bf1 + 2);
    }
    __syncthreads();   // all warps done reading X tile before overwrite with P

    // ---- epilogue: h = r*g - (r*m)*c1 + c2b ; P = gelu_fast(h) fp16 ----
    #pragma unroll
    for (int ti = 0; ti < 2; ++ti) {
        const int row0 = mrow + 16 * ti + (lane >> 2);
        float2 st0 = stat[row0], st1 = stat[row0 + 8];
        float r0f = st0.y, rm0 = st0.y * st0.x;
        float r1f = st1.y, rm1 = st1.y * st1.x;
        char* prow0 = sm + OFF_XN + row0 * STRB;
        char* prow1 = prow0 + 8 * STRB;
        #pragma unroll
        for (int np = 0; np < 4; ++np) {
            int col = ncol + np * 8 + 2 * (lane & 3);
            float2 c1p = *(float2*)(c1s + col);
            float2 c2p = *(float2*)(c2bs + col);
            float2 q0 = __half22float2(*(__half2*)&acc[ti * 4 + np][0]);
            float2 q1 = __half22float2(*(__half2*)&acc[ti * 4 + np][1]);
            float h0 = fmaf(r0f, q0.x, fmaf(-rm0, c1p.x, c2p.x));
            float h1 = fmaf(r0f, q0.y, fmaf(-rm0, c1p.y, c2p.y));
            float h2 = fmaf(r1f, q1.x, fmaf(-rm1, c1p.x, c2p.x));
            float h3 = fmaf(r1f, q1.y, fmaf(-rm1, c1p.y, c2p.y));
            *(uint32_t*)(prow0 + col * 2) = packhf2(gelu_fast(h0), gelu_fast(h1));
            *(uint32_t*)(prow1 + col * 2) = packhf2(gelu_fast(h2), gelu_fast(h3));
        }
    }
    __syncthreads();

    // ---- MMA2: S[16 grp][128 hid] = mask @ P ; warp w owns 8 hidden cols ----
    {
        float a2[4] = {0.f, 0.f, 0.f, 0.f};
        uint32_t aM = smb + OFF_MASK + (lr + (lg & 1) * 8) * STRB + (lg >> 1) * 16;
        uint32_t aP = smb + OFF_XN + ((lane & 7) + ((lane >> 3) & 1) * 8) * STRB + w * 16;
        #pragma unroll
        for (int ks = 0; ks < 8; ++ks) {
            uint32_t mf[4], pf[2];
            LDSM4(mf, aM); aM += 32;
            LDSM2T(pf, aP); aP += 16 * STRB;
            mma16816(a2, mf, pf);
        }
        int grp = lane >> 2;
        int col = w * 8 + 2 * (lane & 3);
        float* dst = &g_hsum[(t * L_ + grp) * D_ + col];
        atomicAdd(dst,     a2[0]);
        atomicAdd(dst + 1, a2[1]);
    }
}

// -------- kernel 2 (merged tail): comp per block, last block does LN + ortho --------
__global__ __launch_bounds__(512) void k_tail(
    const float* __restrict__ w2,   const float* __restrict__ b1,
    const float* __restrict__ b2,   const int*   __restrict__ ne_p,
    const float* __restrict__ lnfw, const float* __restrict__ lnfb,
    float* __restrict__ out, int out_size)
{
    __shared__ __align__(16) float cs[T_ * L_ * CD_];   // 16KB, t-major
    __shared__ __align__(16) float mh[D_];
    __shared__ __align__(16) float part[8][CD_];
    __shared__ float Gm[64];
    __shared__ float Rs[L_], inv[L_];
    __shared__ float dots[49];
    __shared__ int   last;

    const int p   = blockIdx.x;           // t*8 + l
    const int tid = threadIdx.x;
    const int g   = ne_p[0] >> 3;
    if (tid < D_) {
        float h0 = gelu_exact(b1[tid]);
        mh[tid] = (g_hsum[p * D_ + tid] + (float)(g - g_cnt[p]) * h0) / (float)g;
    }
    __syncthreads();
    // zero-restore accumulators for next graph replay (consumed above)
    if (tid < D_) g_hsum[p * D_ + tid] = 0.f;
    if (tid == 0) g_cnt[p] = 0;

    {
        const int c = tid & 63, sl = tid >> 6;   // 8 e-slices of 16
        float a = 0.f;
        #pragma unroll
        for (int i = 0; i < 16; ++i) {
            int e = sl * 16 + i;
            a = fmaf(mh[e], w2[e * CD_ + c], a);
        }
        part[sl][c] = a;
    }
    __syncthreads();
    if (tid < CD_) {
        float s = b2[tid];
        #pragma unroll
        for (int k = 0; k < 8; ++k) s += part[k][tid];
        g_comp[p * CD_ + tid] = s;
    }

    // ---- last-block election ----
    __threadfence();
    if (tid == 0) last = (atomicAdd(&g_bar, 1) == T_ * L_ - 1);
    __syncthreads();
    if (!last) return;
    if (tid == 0) g_bar = 0;            // reset for next replay
    __threadfence();

    // ---- final LN + Gram ortho (single surviving block) ----
    {
        const float4* src = (const float4*)g_comp;
        float4* dst = (float4*)cs;
        dst[tid] = src[tid];
        dst[tid + 512] = src[tid + 512];
    }
    __syncthreads();

    const int w = tid >> 5, lane = tid & 31;
    if (w < 8) {
        const int t = w;
        const float* row = cs + t * 512;
        float s = 0.f;
        for (int i = lane; i < 512; i += 32) s += row[i];
        s = wred(s);
        float m = __shfl_sync(0xffffffffu, s, 0) * (1.0f / 512.0f);
        float v = 0.f;
        for (int i = lane; i < 512; i += 32) { float c0 = row[i] - m; v += c0 * c0; }
        v = wred(v);
        float rstd = rsqrtf(__shfl_sync(0xffffffffu, v, 0) * (1.0f / 512.0f) + 1e-5f);
        for (int i = lane; i < 512; i += 32)
            out[t * 512 + i] = (row[i] - m) * rstd * lnfw[i] + lnfb[i];
    } else {
        const int l = w - 8;
        float r = 0.f, gg = 0.f;
        for (int k = lane; k < 512; k += 32) {
            float v = cs[(k >> 6) * 512 + l * 64 + (k & 63)];
            r += v; gg += v * v;
        }
        r = wred(r); gg = wred(gg);
        if (lane == 0) { Rs[l] = r; Gm[l * 8 + l] = gg; inv[l] = rsqrtf(gg); }
    }
    __syncthreads();

    for (int pp = w; pp < 28; pp += 16) {
        int i = 0, r = pp;
        while (r >= 7 - i) { r -= 7 - i; ++i; }
        int j = i + 1 + r;
        float d = 0.f;
        for (int k = lane; k < 512; k += 32) {
            int off = (k >> 6) * 512 + (k & 63);
            d += cs[off + i * 64] * cs[off + j * 64];
        }
        d = wred(d);
        if (lane == 0) Gm[i * 8 + j] = d;
    }
    __syncthreads();

    if (tid < 49) {
        int i = tid / 7, j = tid % 7 + 1;
        int a = i < j ? i : j, b = i < j ? j : i;
        float gij = Gm[a * 8 + b];
        float num = gij * inv[i] * inv[j];
        float den = Rs[i] * inv[i] + Rs[j] * inv[j];
        float d = num / den;
        dots[tid] = d * d;
    }
    __syncthreads();
    if (tid == 0 && out_size > T_ * L_ * CD_) {
        float s = 0.f;
        #pragma unroll
        for (int pq = 0; pq < 49; ++pq) s += dots[pq];
        out[T_ * L_ * CD_] = s * (1.0f / 49.0f);
    }
}

// -------- launch --------
extern "C" void kernel_launch(void* const* d_in, const int* in_sizes, int n_in,
                              void* d_out, int out_size)
{
    const float* x    = (const float*)d_in[0];
    const float* lnw  = (const float*)d_in[1];
    const float* lnb  = (const float*)d_in[2];
    const float* w1   = (const float*)d_in[3];
    const float* b1   = (const float*)d_in[4];
    const float* w2   = (const float*)d_in[5];
    const float* b2   = (const float*)d_in[6];
    const float* lnfw = (const float*)d_in[7];
    const float* lnfb = (const float*)d_in[8];
    // d_in[9] = padded_node_mask (all-true)
    const int* node_idx = (const int*)d_in[10];
    const int* ne       = (const int*)d_in[11];
    float* out = (float*)d_out;

    cudaFuncSetAttribute(k_main, cudaFuncAttributeMaxDynamicSharedMemorySize, SMEM_SZ);

    k_prep<<<33, 512>>>(w1, lnw, lnb, b1);
    dim3 grid(NTOK_ / 128, T_);
    k_main<<<grid, 512, SMEM_SZ>>>(x, node_idx, ne);
    k_tail<<<T_ * L_, 512>>>(w2, b1, b2, ne, lnfw, lnfb, out, out_size);
}

// round 16
// speedup vs baseline: 1.0819x; 1.0625x over previous
#include <cuda_runtime.h>
#include <cuda_fp16.h>
#include <math.h>
#include <stdint.h>

#define T_     8
#define NTOK_  32768
#define D_     128
#define L_     8
#define CD_    64
#define STRB   272          /* fp16 tile row stride in bytes (136 elems) */

// ---------------- device scratch (zero-initialized at module load) ----------------
__device__ __align__(16) float g_hsum[T_ * L_ * D_];
__device__ __align__(16) float g_comp[T_ * L_ * CD_];
__device__ int   g_cnt [T_ * L_];
__device__ int   g_bar;
__device__ float g_c1  [D_];            // sum_k lnw_k * w1[k,e]
__device__ float g_c2b [D_];            // sum_k lnb_k * w1[k,e] + b1[e]
__device__ __align__(16) __half g_w1img[D_ * 136];  // (lnw .* W1)^T padded [e][k]

// ---------------- helpers ----------------
__device__ __forceinline__ uint32_t smem_u32(const void* p) {
    uint32_t a;
    asm("{ .reg .u64 t; cvta.to.shared.u64 t, %1; cvt.u32.u64 %0, t; }" : "=r"(a) : "l"(p));
    return a;
}
#define LDSM4(f, a) asm volatile( \
    "ldmatrix.sync.aligned.m8n8.x4.shared.b16 {%0,%1,%2,%3}, [%4];" \
    : "=r"((f)[0]), "=r"((f)[1]), "=r"((f)[2]), "=r"((f)[3]) : "r"(a))
#define LDSM2T(f, a) asm volatile( \
    "ldmatrix.sync.aligned.m8n8.x2.trans.shared.b16 {%0,%1}, [%2];" \
    : "=r"((f)[0]), "=r"((f)[1]) : "r"(a))
// fp32-accumulate (MMA2 bucket sums)
__device__ __forceinline__ void mma16816(float* c, const uint32_t* a, const uint32_t* b) {
    asm volatile(
        "mma.sync.aligned.m16n8k16.row.col.f32.f16.f16.f32 "
        "{%0,%1,%2,%3}, {%4,%5,%6,%7}, {%8,%9}, {%0,%1,%2,%3};"
        : "+f"(c[0]), "+f"(c[1]), "+f"(c[2]), "+f"(c[3])
        : "r"(a[0]), "r"(a[1]), "r"(a[2]), "r"(a[3]), "r"(b[0]), "r"(b[1]));
}
// fp16-accumulate (MMA1 main GEMM)
__device__ __forceinline__ void mma16816h(uint32_t* c, const uint32_t* a, const uint32_t* b) {
    asm volatile(
        "mma.sync.aligned.m16n8k16.row.col.f16.f16.f16.f16 "
        "{%0,%1}, {%2,%3,%4,%5}, {%6,%7}, {%0,%1};"
        : "+r"(c[0]), "+r"(c[1])
        : "r"(a[0]), "r"(a[1]), "r"(a[2]), "r"(a[3]), "r"(b[0]), "r"(b[1]));
}
__device__ __forceinline__ uint32_t packhf2(float lo, float hi) {
    uint32_t r;
    asm("cvt.rn.f16x2.f32 %0, %1, %2;" : "=r"(r) : "f"(hi), "f"(lo));
    return r;
}
__device__ __forceinline__ float gelu_exact(float z) {
    return 0.5f * z * (1.0f + erff(z * 0.70710678118654752440f));
}
// ---- packed f32x2 helpers (FFMA2 path) ----
__device__ __forceinline__ unsigned long long pk(float a, float b) {
    unsigned long long r;
    asm("mov.b64 %0, {%1, %2};" : "=l"(r) : "f"(a), "f"(b));
    return r;
}
__device__ __forceinline__ unsigned long long pk2(float c) {
    unsigned long long r;
    asm("mov.b64 %0, {%1, %1};" : "=l"(r) : "f"(c));
    return r;
}
__device__ __forceinline__ unsigned long long fma2(unsigned long long a,
                                                   unsigned long long b,
                                                   unsigned long long c) {
    unsigned long long d;
    asm("fma.rn.f32x2 %0, %1, %2, %3;" : "=l"(d) : "l"(a), "l"(b), "l"(c));
    return d;
}
__device__ __forceinline__ unsigned long long mul2(unsigned long long a,
                                                   unsigned long long b) {
    unsigned long long d;
    asm("mul.rn.f32x2 %0, %1, %2;" : "=l"(d) : "l"(a), "l"(b));
    return d;
}
// paired gelu (same per-lane IEEE math as the scalar gelu_fast): returns fp16x2
__device__ __forceinline__ uint32_t gelu2h(float h0, float h1) {
    float z0 = fminf(fmaxf(h0, -2.5f), 2.5f);
    float z1 = fminf(fmaxf(h1, -2.5f), 2.5f);
    unsigned long long Z  = pk(h0, h1);
    unsigned long long ZC = pk(z0, z1);
    unsigned long long T  = mul2(ZC, ZC);
    unsigned long long Q  = pk2(-4.1226618343100706e-8f);
    Q = fma2(Q, T, pk2( 6.6596941016452680e-7f));
    Q = fma2(Q, T, pk2(-9.4444668655640310e-6f));
    Q = fma2(Q, T, pk2( 1.1543700706522937e-4f));
    Q = fma2(Q, T, pk2(-1.1873282154804544e-3f));
    Q = fma2(Q, T, pk2( 9.9735570100358180e-3f));
    Q = fma2(Q, T, pk2(-6.6490380066905450e-2f));
    Q = fma2(Q, T, pk2( 3.9894228040143270e-1f));
    unsigned long long R = fma2(ZC, Q, pk2(0.5f));
    unsigned long long P = mul2(Z, R);
    float p0, p1;
    asm("mov.b64 {%0, %1}, %2;" : "=f"(p0), "=f"(p1) : "l"(P));
    return packhf2(p0, p1);
}
__device__ __forceinline__ float wred(float v) {
    #pragma unroll
    for (int o = 16; o; o >>= 1) v += __shfl_down_sync(0xffffffffu, v, o);
    return v;
}

// SMEM layout (bytes)
#define OFF_HIST 0
#define OFF_STAT 64          /* 128 x float2 (m, rstd)          */
#define OFF_C1   1088        /* 512B                            */
#define OFF_C2B  1600        /* 512B                            */
#define OFF_MASK 2112        /* 16 x 272 = 4352B                */
#define OFF_XN   6528        /* 128 x 272 (X fp16, later P)     */
#define OFF_W    41344       /* 128 x 272 (W1' ^T fp16)         */
#define SMEM_SZ  76160

// -------- kernel 0: W1' image + c1/c2b vectors --------
__global__ void k_prep(const float* __restrict__ w1, const float* __restrict__ lnw,
                       const float* __restrict__ lnb, const float* __restrict__ b1) {
    __shared__ float pa[512], pb[512];
    const int b = blockIdx.x, tid = threadIdx.x;
    if (b < 32) {
        int i = b * 512 + tid;
        int e = i & 127, k = i >> 7;
        g_w1img[e * 136 + k] = __float2half(lnw[k] * w1[k * 128 + e]);
    } else {
        const int e = tid & 127, j = tid >> 7;
        float a = 0.f, c = 0.f;
        #pragma unroll
        for (int kk = 0; kk < 32; ++kk) {
            int k = j * 32 + kk;
            float wv = w1[k * 128 + e];
            a = fmaf(lnw[k], wv, a);
            c = fmaf(lnb[k], wv, c);
        }
        pa[tid] = a; pb[tid] = c;
        __syncthreads();
        if (tid < 128) {
            g_c1[tid]  = pa[tid] + pa[tid + 128] + pa[tid + 256] + pa[tid + 384];
            g_c2b[tid] = pb[tid] + pb[tid + 128] + pb[tid + 256] + pb[tid + 384] + b1[tid];
        }
    }
}

// -------- kernel 1: x -> HMMA (32x32 tiles) -> LN-affine+gelu -> mask-HMMA sums --------
__global__ __launch_bounds__(512, 2) void k_main(
    const float* __restrict__ x, const int* __restrict__ node_idx,
    const int* __restrict__ ne_p)
{
    extern __shared__ char sm[];
    const uint32_t smb = smem_u32(sm);
    const int tid  = threadIdx.x;
    const int w    = tid >> 5, lane = tid & 31;
    const int t    = blockIdx.y;
    const int base = blockIdx.x * 128;

    int*    hist = (int*)(sm + OFF_HIST);
    float2* stat = (float2*)(sm + OFF_STAT);
    float*  c1s  = (float*)(sm + OFF_C1);
    float*  c2bs = (float*)(sm + OFF_C2B);

    // ---- phase A: zero mask/hist, stage consts, copy W', load x (coalesced) ----
    if (tid < 8) hist[tid] = 0;
    if (tid < 272) ((int4*)(sm + OFF_MASK))[tid] = make_int4(0, 0, 0, 0);
    if (tid < 128)      c1s[tid] = g_c1[tid];
    else if (tid < 256) c2bs[tid - 128] = g_c2b[tid - 128];
    {
        const int4* src = (const int4*)g_w1img;
        int4* dst = (int4*)(sm + OFF_W);
        #pragma unroll
        for (int i = tid; i < 2176; i += 512) dst[i] = src[i];
    }
    // coalesced streaming x load: warp w owns rows [8w, 8w+8)
    float4 xv[8];
    {
        const float4* xp = (const float4*)(x + ((size_t)t * NTOK_ + base + w * 8) * D_) + lane;
        #pragma unroll
        for (int i = 0; i < 8; ++i) xv[i] = __ldcs(xp + i * 32);
    }
    {
        char* rowp = sm + OFF_XN + (w * 8) * STRB + lane * 8;
        #pragma unroll
        for (int i = 0; i < 8; ++i)
            *(uint2*)(rowp + i * STRB) =
                make_uint2(packhf2(xv[i].x, xv[i].y), packhf2(xv[i].z, xv[i].w));
    }
    #pragma unroll
    for (int i = 0; i < 8; ++i) {
        float s  = xv[i].x + xv[i].y + xv[i].z + xv[i].w;
        float s2 = xv[i].x * xv[i].x + xv[i].y * xv[i].y
                 + xv[i].z * xv[i].z + xv[i].w * xv[i].w;
        #pragma unroll
        for (int o = 16; o; o >>= 1) {
            s  += __shfl_down_sync(0xffffffffu, s,  o);
            s2 += __shfl_down_sync(0xffffffffu, s2, o);
        }
        if (lane == 0) {
            float m    = s * (1.0f / 128.0f);
            float rstd = rsqrtf(s2 * (1.0f / 128.0f) - m * m + 1e-5f);
            stat[w * 8 + i] = make_float2(m, rstd);
        }
    }
    __syncthreads();   // mask zero visible

    if (tid < 128) {
        int gsz = ne_p[0] >> 3;
        int gid = node_idx[t * NTOK_ + base + tid] / gsz;
        atomicAdd(&hist[gid], 1);
        *(__half*)(sm + OFF_MASK + gid * STRB + tid * 2) = __float2half(1.0f);
    }
    __syncthreads();   // XN, W, mask, stats all ready

    // ---- MMA1: G[128 tok][128 hid] = X @ W1' (fp16 acc), 32x32 warp tiles ----
    const int mrow = (w & 3) * 32;
    const int ncol = (w >> 2) * 32;
    const int lr = lane & 7, lg = lane >> 3;

    uint32_t acc[8][2];
    #pragma unroll
    for (int j = 0; j < 8; ++j) { acc[j][0] = 0u; acc[j][1] = 0u; }

    uint32_t aA0 = smb + OFF_XN + (mrow + lr + (lg & 1) * 8) * STRB + (lg >> 1) * 16;
    uint32_t aA1 = aA0 + 16 * STRB;
    uint32_t aB0 = smb + OFF_W + (ncol + lr + (lane >> 4) * 8) * STRB + ((lane >> 3) & 1) * 16;
    uint32_t aB1 = aB0 + 16 * STRB;

    #pragma unroll
    for (int ks = 0; ks < 8; ++ks) {
        uint32_t af0[4], af1[4], bf0[4], bf1[4];
        LDSM4(af0, aA0); aA0 += 32;
        LDSM4(af1, aA1); aA1 += 32;
        LDSM4(bf0, aB0); aB0 += 32;
        LDSM4(bf1, aB1); aB1 += 32;
        mma16816h(acc[0], af0, bf0);
        mma16816h(acc[1], af0, bf0 + 2);
        mma16816h(acc[2], af0, bf1);
        mma16816h(acc[3], af0, bf1 + 2);
        mma16816h(acc[4], af1, bf0);
        mma16816h(acc[5], af1, bf0 + 2);
        mma16816h(acc[6], af1, bf1);
        mma16816h(acc[7], af1, bf1 + 2);
    }
    __syncthreads();   // all warps done reading X tile before overwrite with P

    // ---- epilogue: h = r*g - (r*m)*c1 + c2b ; P = gelu2h(h) fp16 (FFMA2 path) ----
    #pragma unroll
    for (int ti = 0; ti < 2; ++ti) {
        const int row0 = mrow + 16 * ti + (lane >> 2);
        float2 st0 = stat[row0], st1 = stat[row0 + 8];
        float r0f = st0.y, rm0 = st0.y * st0.x;
        float r1f = st1.y, rm1 = st1.y * st1.x;
        char* prow0 = sm + OFF_XN + row0 * STRB;
        char* prow1 = prow0 + 8 * STRB;
        #pragma unroll
        for (int np = 0; np < 4; ++np) {
            int col = ncol + np * 8 + 2 * (lane & 3);
            float2 c1p = *(float2*)(c1s + col);
            float2 c2p = *(float2*)(c2bs + col);
            float2 q0 = __half22float2(*(__half2*)&acc[ti * 4 + np][0]);
            float2 q1 = __half22float2(*(__half2*)&acc[ti * 4 + np][1]);
            float h0 = fmaf(r0f, q0.x, fmaf(-rm0, c1p.x, c2p.x));
            float h1 = fmaf(r0f, q0.y, fmaf(-rm0, c1p.y, c2p.y));
            float h2 = fmaf(r1f, q1.x, fmaf(-rm1, c1p.x, c2p.x));
            float h3 = fmaf(r1f, q1.y, fmaf(-rm1, c1p.y, c2p.y));
            *(uint32_t*)(prow0 + col * 2) = gelu2h(h0, h1);
            *(uint32_t*)(prow1 + col * 2) = gelu2h(h2, h3);
        }
    }
    __syncthreads();

    // ---- MMA2: S[16 grp][128 hid] = mask @ P ; warp w owns 8 hidden cols ----
    {
        float a2[4] = {0.f, 0.f, 0.f, 0.f};
        uint32_t aM = smb + OFF_MASK + (lr + (lg & 1) * 8) * STRB + (lg >> 1) * 16;
        uint32_t aP = smb + OFF_XN + ((lane & 7) + ((lane >> 3) & 1) * 8) * STRB + w * 16;
        #pragma unroll
        for (int ks = 0; ks < 8; ++ks) {
            uint32_t mf[4], pf[2];
            LDSM4(mf, aM); aM += 32;
            LDSM2T(pf, aP); aP += 16 * STRB;
            mma16816(a2, mf, pf);
        }
        int grp = lane >> 2;
        int col = w * 8 + 2 * (lane & 3);
        float* dst = &g_hsum[(t * L_ + grp) * D_ + col];
        atomicAdd(dst,     a2[0]);
        atomicAdd(dst + 1, a2[1]);
    }
    if (tid < 8) atomicAdd(&g_cnt[t * L_ + tid], hist[tid]);
}

// -------- kernel 2 (merged tail): comp per block, last block does LN + ortho --------
__global__ __launch_bounds__(512) void k_tail(
    const float* __restrict__ w2,   const float* __restrict__ b1,
    const float* __restrict__ b2,   const int*   __restrict__ ne_p,
    const float* __restrict__ lnfw, const float* __restrict__ lnfb,
    float* __restrict__ out, int out_size)
{
    __shared__ __align__(16) float cs[T_ * L_ * CD_];   // 16KB, t-major
    __shared__ __align__(16) float mh[D_];
    __shared__ __align__(16) float part[8][CD_];
    __shared__ float Gm[64];
    __shared__ float Rs[L_], inv[L_];
    __shared__ float dots[49];
    __shared__ int   last;

    const int p   = blockIdx.x;           // t*8 + l
    const int tid = threadIdx.x;
    const int g   = ne_p[0] >> 3;
    if (tid < D_) {
        float h0 = gelu_exact(b1[tid]);
        mh[tid] = (g_hsum[p * D_ + tid] + (float)(g - g_cnt[p]) * h0) / (float)g;
    }
    __syncthreads();
    // zero-restore accumulators for next graph replay (consumed above)
    if (tid < D_) g_hsum[p * D_ + tid] = 0.f;
    if (tid == 0) g_cnt[p] = 0;

    {
        const int c = tid & 63, sl = tid >> 6;   // 8 e-slices of 16
        float a = 0.f;
        #pragma unroll
        for (int i = 0; i < 16; ++i) {
            int e = sl * 16 + i;
            a = fmaf(mh[e], w2[e * CD_ + c], a);
        }
        part[sl][c] = a;
    }
    __syncthreads();
    if (tid < CD_) {
        float s = b2[tid];
        #pragma unroll
        for (int k = 0; k < 8; ++k) s += part[k][tid];
        g_comp[p * CD_ + tid] = s;
    }

    // ---- last-block election ----
    __threadfence();
    if (tid == 0) last = (atomicAdd(&g_bar, 1) == T_ * L_ - 1);
    __syncthreads();
    if (!last) return;
    if (tid == 0) g_bar = 0;            // reset for next replay
    __threadfence();

    // ---- final LN + Gram ortho (single surviving block) ----
    {
        const float4* src = (const float4*)g_comp;
        float4* dst = (float4*)cs;
        dst[tid] = src[tid];
        dst[tid + 512] = src[tid + 512];
    }
    __syncthreads();

    const int w = tid >> 5, lane = tid & 31;
    if (w < 8) {
        const int t = w;
        const float* row = cs + t * 512;
        float s = 0.f;
        for (int i = lane; i < 512; i += 32) s += row[i];
        s = wred(s);
        float m = __shfl_sync(0xffffffffu, s, 0) * (1.0f / 512.0f);
        float v = 0.f;
        for (int i = lane; i < 512; i += 32) { float c0 = row[i] - m; v += c0 * c0; }
        v = wred(v);
        float rstd = rsqrtf(__shfl_sync(0xffffffffu, v, 0) * (1.0f / 512.0f) + 1e-5f);
        for (int i = lane; i < 512; i += 32)
            out[t * 512 + i] = (row[i] - m) * rstd * lnfw[i] + lnfb[i];
    } else {
        const int l = w - 8;
        float r = 0.f, gg = 0.f;
        for (int k = lane; k < 512; k += 32) {
            float v = cs[(k >> 6) * 512 + l * 64 + (k & 63)];
            r += v; gg += v * v;
        }
        r = wred(r); gg = wred(gg);
        if (lane == 0) { Rs[l] = r; Gm[l * 8 + l] = gg; inv[l] = rsqrtf(gg); }
    }
    __syncthreads();

    for (int pp = w; pp < 28; pp += 16) {
        int i = 0, r = pp;
        while (r >= 7 - i) { r -= 7 - i; ++i; }
        int j = i + 1 + r;
        float d = 0.f;
        for (int k = lane; k < 512; k += 32) {
            int off = (k >> 6) * 512 + (k & 63);
            d += cs[off + i * 64] * cs[off + j * 64];
        }
        d = wred(d);
        if (lane == 0) Gm[i * 8 + j] = d;
    }
    __syncthreads();

    if (tid < 49) {
        int i = tid / 7, j = tid % 7 + 1;
        int a = i < j ? i : j, b = i < j ? j : i;
        float gij = Gm[a * 8 + b];
        float num = gij * inv[i] * inv[j];
        float den = Rs[i] * inv[i] + Rs[j] * inv[j];
        float d = num / den;
        dots[tid] = d * d;
    }
    __syncthreads();
    if (tid == 0 && out_size > T_ * L_ * CD_) {
        float s = 0.f;
        #pragma unroll
        for (int pq = 0; pq < 49; ++pq) s += dots[pq];
        out[T_ * L_ * CD_] = s * (1.0f / 49.0f);
    }
}

// -------- launch --------
extern "C" void kernel_launch(void* const* d_in, const int* in_sizes, int n_in,
                              void* d_out, int out_size)
{
    const float* x    = (const float*)d_in[0];
    const float* lnw  = (const float*)d_in[1];
    const float* lnb  = (const float*)d_in[2];
    const float* w1   = (const float*)d_in[3];
    const float* b1   = (const float*)d_in[4];
    const float* w2   = (const float*)d_in[5];
    const float* b2   = (const float*)d_in[6];
    const float* lnfw = (const float*)d_in[7];
    const float* lnfb = (const float*)d_in[8];
    // d_in[9] = padded_node_mask (all-true)
    const int* node_idx = (const int*)d_in[10];
    const int* ne       = (const int*)d_in[11];
    float* out = (float*)d_out;

    cudaFuncSetAttribute(k_main, cudaFuncAttributeMaxDynamicSharedMemorySize, SMEM_SZ);

    k_prep<<<33, 512>>>(w1, lnw, lnb, b1);
    dim3 grid(NTOK_ / 128, T_);
    k_main<<<grid, 512, SMEM_SZ>>>(x, node_idx, ne);
    k_tail<<<T_ * L_, 512>>>(w2, b1, b2, ne, lnfw, lnfb, out, out_size);
}